// round 10
// baseline (speedup 1.0000x reference)
#include <cuda_runtime.h>
#include <cuda_bf16.h>
#include <cstdint>
#include <cstddef>

#define T_STEPS 2048
#define OFF 8

typedef unsigned long long ull;

// ---------------------------------------------------------------------------
// Device-global scratch (no allocation allowed). Tagged history rings:
// each 8B word = {hi32: tag = slot+1, lo32: f32 h}. Slot = t + OFF.
// ---------------------------------------------------------------------------
__device__ ull g_hist0[(T_STEPS + OFF) * 128];
__device__ ull g_hist1[(T_STEPS + OFF) * 128];
__device__ ull g_hist2[(T_STEPS + OFF) * 128];
__device__ ull g_hist3[(T_STEPS + OFF) * 256];
__device__ float g_zx[(size_t)T_STEPS * 512];   // Wih0@x + bih0 + bhh0

// ---------------------------------------------------------------------------
__device__ __forceinline__ ull ldr(const ull* p) {
    ull v;
    asm volatile("ld.relaxed.gpu.global.u64 %0, [%1];" : "=l"(v) : "l"(p) : "memory");
    return v;
}
__device__ __forceinline__ void str(ull* p, ull v) {
    asm volatile("st.relaxed.gpu.global.u64 [%0], %1;" :: "l"(p), "l"(v) : "memory");
}
__device__ __forceinline__ ull pack_hv(float h, unsigned tag) {
    return ((ull)tag << 32) | (ull)__float_as_uint(h);
}
__device__ __forceinline__ float sigf(float x) {
    return __fdividef(1.0f, 1.0f + __expf(-x));
}
__device__ __forceinline__ float tanh_f(float x) {
    return 2.0f * sigf(2.0f * x) - 1.0f;
}

// ---------------------------------------------------------------------------
// Init: zero all tags, seed initial h states. Must run every graph replay.
// ---------------------------------------------------------------------------
__device__ void init_one(ull* hist, int DOUT, int DIL, const float* h0,
                         int gid, int gs) {
    int N = (T_STEPS + OFF) * DOUT;
    for (int i = gid; i < N; i += gs) {
        int s = i / DOUT;
        int j = i - s * DOUT;
        ull v = 0ull;
        if (s >= OFF - DIL && s < OFF)
            v = pack_hv(h0[(s - (OFF - DIL)) * DOUT + j], (unsigned)(s + 1));
        hist[i] = v;
    }
}

__global__ void init_hist_kernel(const float* __restrict__ h00,
                                 const float* __restrict__ h01,
                                 const float* __restrict__ h02,
                                 const float* __restrict__ h03) {
    int gid = blockIdx.x * blockDim.x + threadIdx.x;
    int gs = gridDim.x * blockDim.x;
    init_one(g_hist0, 128, 1, h00, gid, gs);
    init_one(g_hist1, 128, 2, h01, gid, gs);
    init_one(g_hist2, 128, 4, h02, gid, gs);
    init_one(g_hist3, 256, 8, h03, gid, gs);
}

// ---------------------------------------------------------------------------
// Layer-0 input projection: g_zx[t][r] = sum_k Wih0[r][k]*x[t][k] + bih0[r] + bhh0[r]
// x:[2048,256] row-major, W:[512,256] row-major. BM=128, BN=64, BK=16, 256 thr.
// ---------------------------------------------------------------------------
__global__ void __launch_bounds__(256) xproj_kernel(const float* __restrict__ x,
                                                    const float* __restrict__ W,
                                                    const float* __restrict__ b1,
                                                    const float* __restrict__ b2) {
    __shared__ float Xs[16][129];
    __shared__ float Ws[16][65];
    const int tid = threadIdx.x;
    const int m0 = blockIdx.x * 128;
    const int n0 = blockIdx.y * 64;
    const int tm = (tid >> 4) * 8;
    const int tn = (tid & 15) * 4;

    float acc[8][4];
#pragma unroll
    for (int i = 0; i < 8; i++)
#pragma unroll
        for (int j = 0; j < 4; j++) acc[i][j] = 0.0f;

    for (int k0 = 0; k0 < 256; k0 += 16) {
#pragma unroll
        for (int i = 0; i < 2; i++) {
            int f = tid + i * 256;
            int m = f >> 2;
            int kq = (f & 3) * 4;
            float4 v = *(const float4*)(x + (size_t)(m0 + m) * 256 + k0 + kq);
            Xs[kq + 0][m] = v.x; Xs[kq + 1][m] = v.y;
            Xs[kq + 2][m] = v.z; Xs[kq + 3][m] = v.w;
        }
        {
            int r = tid >> 2;
            int kq = (tid & 3) * 4;
            float4 v = *(const float4*)(W + (size_t)(n0 + r) * 256 + k0 + kq);
            Ws[kq + 0][r] = v.x; Ws[kq + 1][r] = v.y;
            Ws[kq + 2][r] = v.z; Ws[kq + 3][r] = v.w;
        }
        __syncthreads();
#pragma unroll
        for (int k = 0; k < 16; k++) {
            float rm[8], rn[4];
#pragma unroll
            for (int i = 0; i < 8; i++) rm[i] = Xs[k][tm + i];
#pragma unroll
            for (int j = 0; j < 4; j++) rn[j] = Ws[k][tn + j];
#pragma unroll
            for (int i = 0; i < 8; i++)
#pragma unroll
                for (int j = 0; j < 4; j++)
                    acc[i][j] = fmaf(rm[i], rn[j], acc[i][j]);
        }
        __syncthreads();
    }
#pragma unroll
    for (int i = 0; i < 8; i++)
#pragma unroll
        for (int j = 0; j < 4; j++) {
            int r = n0 + tn + j;
            g_zx[(size_t)(m0 + tm + i) * 512 + r] = acc[i][j] + b1[r] + b2[r];
        }
}

// ---------------------------------------------------------------------------
// Persistent per-layer recurrence.
// MODE: 1 = layer 0 (uses g_zx, DIN=0), 0 = middle, 2 = layer 3 (writes out).
// G CTAs per layer; each owns CHUNK = DOUT/G h-elems => ROWS = 4*CHUNK z-rows.
// Weight slice fully register-resident; 256 threads = 8 warps.
// ---------------------------------------------------------------------------
template <int DIN, int DOUT, int G, int DILN, int MODE>
__device__ void run_layer(int cta,
                          const float* __restrict__ Wih,
                          const float* __restrict__ Whh,
                          const float* __restrict__ bih,
                          const float* __restrict__ bhh,
                          const float* __restrict__ c0,
                          const ull* hin, ull* hown, float* out, float* sbuf) {
    constexpr int CHUNK = DOUT / G;       // 16 (L0) or 8
    constexpr int ROWS  = 4 * CHUNK;      // 64 or 32
    constexpr int RPW   = ROWS / 8;       // rows per warp: 8 or 4
    constexpr int COLS  = DIN + DOUT;     // 128 / 256 / 384
    constexpr int CPL   = COLS / 32;      // cols per lane: 4 / 8 / 12

    float* act = sbuf;          // [0,384)
    float* zsh = sbuf + 384;    // [384,448)
    float* csh = sbuf + 448;    // [448,512): c state [DILN][CHUNK]

    const int tid  = threadIdx.x;
    const int lane = tid & 31;
    const int w    = tid >> 5;

    // ---- weight slice into registers ----
    float wreg[RPW * CPL];
#pragma unroll
    for (int r = 0; r < RPW; r++) {
        int lr = w * RPW + r;
        int g = lr / CHUNK;
        int e = lr - g * CHUNK;
        int zr = g * DOUT + cta * CHUNK + e;
#pragma unroll
        for (int k = 0; k < CPL; k++) {
            int j = lane + 32 * k;
            float wv;
            if (DIN > 0 && j < DIN) wv = Wih[(size_t)zr * DIN + j];
            else                    wv = Whh[(size_t)zr * DOUT + (j - DIN)];
            wreg[r * CPL + k] = wv;
        }
    }

    // ---- biases (layer 0: folded into g_zx) ----
    float b[4] = {0.f, 0.f, 0.f, 0.f};
    if (MODE != 1 && tid < CHUNK) {
#pragma unroll
        for (int g = 0; g < 4; g++) {
            int zr = g * DOUT + cta * CHUNK + tid;
            b[g] = bih[zr] + bhh[zr];
        }
    }

    // ---- initial c ----
    if (tid < CHUNK * DILN) {
        int k = tid / CHUNK, e = tid - k * CHUNK;
        csh[tid] = c0[k * DOUT + cta * CHUNK + e];
    }
    __syncthreads();

    // ---- recurrence ----
    for (int t = 0; t < T_STEPS; t++) {
        float zxv[4] = {0.f, 0.f, 0.f, 0.f};
        if (MODE == 1 && tid < CHUNK) {
#pragma unroll
            for (int g = 0; g < 4; g++)
                zxv[g] = __ldg(&g_zx[(size_t)t * 512 + g * 128 + cta * CHUNK + tid]);
        }

        // stage activations: [0,DIN) = layer-below h at t; [DIN,COLS) = own h at t-DILN
        for (int idx = tid; idx < COLS; idx += 256) {
            const ull* p;
            unsigned ex;
            if (DIN > 0 && idx < DIN) {
                p  = hin + (size_t)(t + OFF) * DIN + idx;
                ex = (unsigned)(t + OFF + 1);
            } else {
                p  = hown + (size_t)(t + OFF - DILN) * DOUT + (idx - DIN);
                ex = (unsigned)(t + OFF - DILN + 1);
            }
            ull v = ldr(p);
            while ((unsigned)(v >> 32) != ex) v = ldr(p);
            act[idx] = __uint_as_float((unsigned)v);
        }
        __syncthreads();

        // GEMV: register weights x smem activations
        float acc[RPW];
#pragma unroll
        for (int r = 0; r < RPW; r++) acc[r] = 0.0f;
#pragma unroll
        for (int k = 0; k < CPL; k++) {
            float a = act[lane + 32 * k];
#pragma unroll
            for (int r = 0; r < RPW; r++)
                acc[r] = fmaf(wreg[r * CPL + k], a, acc[r]);
        }
#pragma unroll
        for (int r = 0; r < RPW; r++) {
#pragma unroll
            for (int d = 16; d > 0; d >>= 1)
                acc[r] += __shfl_xor_sync(0xffffffffu, acc[r], d);
        }
#pragma unroll
        for (int r = 0; r < RPW; r++)
            if (lane == r) zsh[w * RPW + r] = acc[r];
        __syncthreads();

        // gates + state update + tagged publish
        if (tid < CHUNK) {
            float zi = zsh[tid];
            float zf = zsh[CHUNK + tid];
            float zg = zsh[2 * CHUNK + tid];
            float zo = zsh[3 * CHUNK + tid];
            if (MODE == 1) { zi += zxv[0]; zf += zxv[1]; zg += zxv[2]; zo += zxv[3]; }
            else           { zi += b[0];   zf += b[1];   zg += b[2];   zo += b[3];  }
            float ig = sigf(zi);
            float fg = sigf(zf);
            float gg = tanh_f(zg);
            float og = sigf(zo);
            int k = t & (DILN - 1);
            float c2 = fg * csh[k * CHUNK + tid] + ig * gg;
            csh[k * CHUNK + tid] = c2;
            float h2 = og * tanh_f(c2);
            str(hown + (size_t)(t + OFF) * DOUT + cta * CHUNK + tid,
                pack_hv(h2, (unsigned)(t + OFF + 1)));
            if (MODE == 2) out[(size_t)t * 256 + cta * CHUNK + tid] = h2;
        }
        // note: next iter's post-staging barrier orders zsh/act reuse (gate thread
        // must arrive there, which happens only after its zsh reads complete)
    }
}

// ---------------------------------------------------------------------------
struct DP {
    const float *Whh0;
    const float *Wih1, *Whh1, *bih1, *bhh1;
    const float *Wih2, *Whh2, *bih2, *bhh2;
    const float *Wih3, *Whh3, *bih3, *bhh3;
    const float *c00, *c01, *c02, *c03;
    float* out;
};

// 72 CTAs: [0,8)=L0, [8,24)=L1, [24,40)=L2, [40,72)=L3. Single wave (<=148 SMs).
__global__ void __launch_bounds__(256) drnn_kernel(DP p) {
    __shared__ float sbuf[512];
    int b = blockIdx.x;
    if (b < 8) {
        run_layer<0, 128, 8, 1, 1>(b, nullptr, p.Whh0, nullptr, nullptr, p.c00,
                                   nullptr, g_hist0, nullptr, sbuf);
    } else if (b < 24) {
        run_layer<128, 128, 16, 2, 0>(b - 8, p.Wih1, p.Whh1, p.bih1, p.bhh1, p.c01,
                                      g_hist0, g_hist1, nullptr, sbuf);
    } else if (b < 40) {
        run_layer<128, 128, 16, 4, 0>(b - 24, p.Wih2, p.Whh2, p.bih2, p.bhh2, p.c02,
                                      g_hist1, g_hist2, nullptr, sbuf);
    } else {
        run_layer<128, 256, 32, 8, 2>(b - 40, p.Wih3, p.Whh3, p.bih3, p.bhh3, p.c03,
                                      g_hist2, g_hist3, p.out, sbuf);
    }
}

// ---------------------------------------------------------------------------
extern "C" void kernel_launch(void* const* d_in, const int* in_sizes, int n_in,
                              void* d_out, int out_size) {
    // Input index maps: detect interleaved (x,[W..,h0,c0]*4) vs grouped
    // (x, weights*16, states*8) ordering via in_sizes[5]:
    //   interleaved -> h0_0 (128), grouped -> Wih1 (65536).
    int iW[4], iU[4], ibi[4], ibh[4], ih[4], ic[4];
    if (in_sizes[5] == 128) {            // interleaved (setup_inputs dict order)
        for (int i = 0; i < 4; i++) {
            int base = 1 + i * 6;
            iW[i] = base; iU[i] = base + 1; ibi[i] = base + 2; ibh[i] = base + 3;
            ih[i] = base + 4; ic[i] = base + 5;
        }
    } else {                             // grouped (reference() arg order)
        for (int i = 0; i < 4; i++) {
            iW[i] = 1 + 4 * i; iU[i] = 2 + 4 * i;
            ibi[i] = 3 + 4 * i; ibh[i] = 4 + 4 * i;
            ih[i] = 17 + 2 * i; ic[i] = 18 + 2 * i;
        }
    }

    const float* x = (const float*)d_in[0];

    init_hist_kernel<<<256, 256>>>((const float*)d_in[ih[0]],
                                   (const float*)d_in[ih[1]],
                                   (const float*)d_in[ih[2]],
                                   (const float*)d_in[ih[3]]);

    dim3 g(16, 8);
    xproj_kernel<<<g, 256>>>(x, (const float*)d_in[iW[0]],
                             (const float*)d_in[ibi[0]],
                             (const float*)d_in[ibh[0]]);

    DP p;
    p.Whh0 = (const float*)d_in[iU[0]];
    p.Wih1 = (const float*)d_in[iW[1]]; p.Whh1 = (const float*)d_in[iU[1]];
    p.bih1 = (const float*)d_in[ibi[1]]; p.bhh1 = (const float*)d_in[ibh[1]];
    p.Wih2 = (const float*)d_in[iW[2]]; p.Whh2 = (const float*)d_in[iU[2]];
    p.bih2 = (const float*)d_in[ibi[2]]; p.bhh2 = (const float*)d_in[ibh[2]];
    p.Wih3 = (const float*)d_in[iW[3]]; p.Whh3 = (const float*)d_in[iU[3]];
    p.bih3 = (const float*)d_in[ibi[3]]; p.bhh3 = (const float*)d_in[ibh[3]];
    p.c00 = (const float*)d_in[ic[0]];
    p.c01 = (const float*)d_in[ic[1]];
    p.c02 = (const float*)d_in[ic[2]];
    p.c03 = (const float*)d_in[ic[3]];
    p.out = (float*)d_out;

    drnn_kernel<<<72, 256>>>(p);
}